// round 7
// baseline (speedup 1.0000x reference)
#include <cuda_runtime.h>
#include <cuda_bf16.h>
#include <math.h>
#include <stdint.h>

#define BATCH 32
#define CH    96
#define HH    56
#define WW    56
#define HW    3136
#define CHW   301056
#define TOT   9633792
#define EPSV  1e-5f

// ---------------- scratch ----------------------------------------------------
__device__ float g_h1[TOT];
__device__ float g_d [TOT];
__device__ float g_xlr[TOT];
__device__ float g_xtd[TOT];
__device__ float g_t [TOT];
__device__ float g_p1[BATCH * 25 * 2];
__device__ float g_p2[BATCH * 192 * 2];
__device__ float g_p3[BATCH * 25 * 2];

__device__ __forceinline__ float gelu_f(float x) {
    return 0.5f * x * (1.0f + erff(x * 0.7071067811865476f));
}

__device__ __forceinline__ uint32_t pack2(float lo, float hi) {
    __nv_bfloat162 t = __floats2bfloat162_rn(lo, hi);
    return *(uint32_t*)&t;
}

__device__ __forceinline__ void mma16816(float& d0, float& d1, float& d2, float& d3,
                                         uint32_t a0, uint32_t a1, uint32_t a2, uint32_t a3,
                                         uint32_t b0, uint32_t b1) {
    asm volatile(
        "mma.sync.aligned.m16n8k16.row.col.f32.bf16.bf16.f32 "
        "{%0,%1,%2,%3}, {%4,%5,%6,%7}, {%8,%9}, {%0,%1,%2,%3};"
        : "+f"(d0), "+f"(d1), "+f"(d2), "+f"(d3)
        : "r"(a0), "r"(a1), "r"(a2), "r"(a3), "r"(b0), "r"(b1));
}

// warp-0 inline GN stats from npart (sum,sumsq) pairs -> red[0]=mu, red[1]=rstd
__device__ __forceinline__ void stats_warp0(const float* __restrict__ part,
                                            int b, int npart, int warp, int lane,
                                            float* red) {
    if (warp == 0) {
        float s1 = 0.f, s2 = 0.f;
        for (int i = lane; i < npart; i += 32) {
            s1 += part[((size_t)b * npart + i) * 2];
            s2 += part[((size_t)b * npart + i) * 2 + 1];
        }
#pragma unroll
        for (int off = 16; off > 0; off >>= 1) {
            s1 += __shfl_xor_sync(0xFFFFFFFFu, s1, off);
            s2 += __shfl_xor_sync(0xFFFFFFFFu, s2, off);
        }
        if (lane == 0) {
            float mu  = s1 / (float)CHW;
            float var = s2 / (float)CHW - mu * mu;
            red[0] = mu;
            red[1] = rsqrtf(var + EPSV);
        }
    }
    __syncthreads();
}

// A-operand: weight 16x16 bf16 hi/lo fragments from global (row o_row)
__device__ __forceinline__ void load_afrags(const float* __restrict__ w, int o_row,
                                            int tig, uint32_t aH[6][4], uint32_t aL[6][4]) {
    const float* w0 = w + (size_t)o_row * CH;
#pragma unroll
    for (int s = 0; s < 6; s++) {
        const int c0 = s * 16 + 2 * tig;
#pragma unroll
        for (int q = 0; q < 4; q++) {
            const int roff = (q & 1) ? 8 * CH : 0;
            const int coff = (q & 2) ? 8 : 0;
            const float f0 = __ldg(&w0[roff + c0 + coff]);
            const float f1 = __ldg(&w0[roff + c0 + coff + 1]);
            const __nv_bfloat16 h0 = __float2bfloat16_rn(f0);
            const __nv_bfloat16 h1 = __float2bfloat16_rn(f1);
            aH[s][q] = pack2(__bfloat162float(h0), __bfloat162float(h1));
            aL[s][q] = pack2(f0 - __bfloat162float(h0), f1 - __bfloat162float(h1));
        }
    }
}

// B row stride: 6 s-groups * 4 tig * 16B = 384B, padded to 448 (bank-disjoint phases)
#define RSTR 448

// ---------------- 96x96 conv1x1 (mma.sync, split-bf16, LDS.128 B) ------------
// INM: 2 = gn-affine input (stats inline from part_in, npart=25)
// OUTM: 1 = gelu. PART: emit partials. ACC: += existing out.
template<int INM, int OUTM, int PART, int ACC>
__global__ void __launch_bounds__(192, 3) gemm_mma(
    const float* __restrict__ in, const float* __restrict__ w,
    const float* __restrict__ bias, float* __restrict__ out,
    const float* __restrict__ part_in, const float* __restrict__ gw,
    const float* __restrict__ gb, float* __restrict__ part)
{
    extern __shared__ char dsm[];
    char* bsm = dsm;                               // [128 px][448 B]
    float* red = (float*)(dsm + 128 * RSTR);

    const int b    = blockIdx.y;
    const int p0   = blockIdx.x * 128;
    const int tid  = threadIdx.x;
    const int warp = tid >> 5, lane = tid & 31;
    const int gid  = lane >> 2, tig = lane & 3;
    const int o0   = warp * 16;

    float mu = 0.f, rs = 0.f;
    if (INM == 2) {
        stats_warp0(part_in, b, 25, warp, lane, red);
        mu = red[0]; rs = red[1];
        __syncthreads();
    }

    // ---- B fill: [px][s*64 + tig*16 + {hi:0,lo:8} + delta*4 + eps*2] -------
    const float* inb = in + (size_t)b * CHW + p0;
    for (int i = tid; i < CH * 128; i += 192) {
        const int px = i & 127, c = i >> 7;
        float v = 0.f;
        if (p0 + px < HW) v = inb[(size_t)c * HW + px];
        if (INM == 2) { float a = rs * gw[c]; v = v * a + (gb[c] - mu * a); }
        const __nv_bfloat16 h = __float2bfloat16_rn(v);
        const __nv_bfloat16 l = __float2bfloat16_rn(v - __bfloat162float(h));
        const int s = c >> 4, r = c & 15;
        const int t = (r & 7) >> 1, dlt = r >> 3, eps = r & 1;
        char* p = bsm + px * RSTR + s * 64 + t * 16 + dlt * 4 + eps * 2;
        *(__nv_bfloat16*)p       = h;
        *(__nv_bfloat16*)(p + 8) = l;
    }

    uint32_t aH[6][4], aL[6][4];
    load_afrags(w, o0 + gid, tig, aH, aL);
    __syncthreads();

    const float bias0 = bias[o0 + gid];
    const float bias1 = bias[o0 + gid + 8];
    float s1 = 0.f, s2 = 0.f;
    float* ob = out + (size_t)b * CHW;

    for (int nt = 0; nt < 16; nt++) {
        float d0 = 0.f, d1 = 0.f, d2 = 0.f, d3 = 0.f;
        const char* bp = bsm + (nt * 8 + gid) * RSTR + tig * 16;
#pragma unroll
        for (int s = 0; s < 6; s++) {
            const uint4 q = *(const uint4*)(bp + s * 64);
            mma16816(d0, d1, d2, d3, aH[s][0], aH[s][1], aH[s][2], aH[s][3], q.x, q.y);
            mma16816(d0, d1, d2, d3, aL[s][0], aL[s][1], aL[s][2], aL[s][3], q.x, q.y);
            mma16816(d0, d1, d2, d3, aH[s][0], aH[s][1], aH[s][2], aH[s][3], q.z, q.w);
        }
        const int px = p0 + nt * 8 + 2 * tig;
        if (px < HW) {
            float v00 = d0 + bias0, v01 = d1 + bias0;
            float v10 = d2 + bias1, v11 = d3 + bias1;
            if (OUTM == 1) {
                v00 = gelu_f(v00); v01 = gelu_f(v01);
                v10 = gelu_f(v10); v11 = gelu_f(v11);
            }
            float* p00 = ob + (size_t)(o0 + gid) * HW + px;
            float* p10 = ob + (size_t)(o0 + gid + 8) * HW + px;
            if (ACC) {
                float2 t0 = *(float2*)p00; v00 += t0.x; v01 += t0.y;
                float2 t1 = *(float2*)p10; v10 += t1.x; v11 += t1.y;
            }
            *(float2*)p00 = make_float2(v00, v01);
            *(float2*)p10 = make_float2(v10, v11);
            if (PART) {
                s1 += v00 + v01 + v10 + v11;
                s2 += v00 * v00 + v01 * v01 + v10 * v10 + v11 * v11;
            }
        }
    }

    if (PART) {
#pragma unroll
        for (int off = 16; off > 0; off >>= 1) {
            s1 += __shfl_xor_sync(0xFFFFFFFFu, s1, off);
            s2 += __shfl_xor_sync(0xFFFFFFFFu, s2, off);
        }
        __syncthreads();
        if (lane == 0) { red[warp] = s1; red[8 + warp] = s2; }
        __syncthreads();
        if (tid == 0) {
            float t1 = 0.f, t2 = 0.f;
#pragma unroll
            for (int i = 0; i < 6; i++) { t1 += red[i]; t2 += red[8 + i]; }
            float* pp = part + ((size_t)b * gridDim.x + blockIdx.x) * 2;
            pp[0] = t1; pp[1] = t2;
        }
    }
}

// ---------------- depthwise 3x3, fused GN1+GELU (stats inline) ---------------
__global__ void __launch_bounds__(256) dw_k(
    const float* __restrict__ in, const float* __restrict__ part_in,
    const float* __restrict__ gw, const float* __restrict__ gb,
    const float* __restrict__ dww, const float* __restrict__ dwb,
    float* __restrict__ out, float* __restrict__ part)
{
    __shared__ float tile[30][58];
    __shared__ float red[512];
    const int rt = blockIdx.x;
    const int c  = blockIdx.y;
    const int b  = blockIdx.z;
    const int tid = threadIdx.x;
    const int warp = tid >> 5, lane = tid & 31;

    stats_warp0(part_in, b, 25, warp, lane, red);
    const float mu = red[0], rs = red[1];
    __syncthreads();

    const float a  = rs * gw[c];
    const float bb = gb[c] - mu * a;
    const float* inb = in + (size_t)(b * CH + c) * HW;
    const int r0 = rt * 28;

    for (int i = tid; i < 30 * 58; i += 256) {
        int rr = i / 58, cc = i % 58;
        int gr = r0 - 1 + rr, gc = cc - 1;
        float v = 0.f;
        if (gr >= 0 && gr < HH && gc >= 0 && gc < WW)
            v = gelu_f(inb[gr * WW + gc] * a + bb);
        tile[rr][cc] = v;
    }
    float wd[9];
#pragma unroll
    for (int i = 0; i < 9; i++) wd[i] = dww[c * 9 + i];
    const float bd = dwb[c];
    __syncthreads();

    float s1 = 0.f, s2 = 0.f;
    for (int p = tid; p < 28 * 56; p += 256) {
        int lr = p / 56, lc = p % 56;
        float accv = bd;
#pragma unroll
        for (int i = 0; i < 3; i++)
#pragma unroll
            for (int j = 0; j < 3; j++)
                accv = fmaf(wd[i * 3 + j], tile[lr + i][lc + j], accv);
        out[(size_t)(b * CH + c) * HW + (r0 + lr) * WW + lc] = accv;
        s1 += accv; s2 += accv * accv;
    }
    red[tid] = s1; red[256 + tid] = s2;
    __syncthreads();
    for (int off = 128; off > 0; off >>= 1) {
        if (tid < off) {
            red[tid] += red[tid + off];
            red[256 + tid] += red[256 + tid + off];
        }
        __syncthreads();
    }
    if (tid == 0) {
        float* pp = part + ((size_t)b * 192 + c * 2 + rt) * 2;
        pp[0] = red[0]; pp[1] = red[256];
    }
}

// ---------------- fused LIF (stats inline, H and W scans, 4x4 tile) ----------
__global__ void __launch_bounds__(256) lif_k(
    const float* __restrict__ in, const float* __restrict__ part_in,
    const float* __restrict__ gw, const float* __restrict__ gb,
    const float* __restrict__ tau1_p, const float* __restrict__ vth1_p,
    const float* __restrict__ tau2_p, const float* __restrict__ vth2_p,
    float* __restrict__ xlr, float* __restrict__ xtd)
{
    __shared__ float red[2];
    const int tid = threadIdx.x;
    const int warp = tid >> 5, lane = tid & 31;
    const int idx = blockIdx.x * 256 + tid;

    const int wg = idx % 14;
    const int hg = (idx / 14) % 14;
    const int c  = (idx / 196) % CH;
    const int b  = idx / (196 * CH);
    const bool ok = idx < BATCH * CH * 14 * 14;

    const int b0 = (blockIdx.x * 256) / 18816;
    if (warp == 0) {
        float s1 = 0.f, s2 = 0.f;
        for (int i = lane; i < 192; i += 32) {
            s1 += part_in[((size_t)b0 * 192 + i) * 2];
            s2 += part_in[((size_t)b0 * 192 + i) * 2 + 1];
        }
#pragma unroll
        for (int off = 16; off > 0; off >>= 1) {
            s1 += __shfl_xor_sync(0xFFFFFFFFu, s1, off);
            s2 += __shfl_xor_sync(0xFFFFFFFFu, s2, off);
        }
        if (lane == 0) {
            float m = s1 / (float)CHW;
            red[0] = m;
            red[1] = rsqrtf(s2 / (float)CHW - m * m + EPSV);
        }
    }
    __syncthreads();
    float mu = red[0], rs = red[1];
    if (ok && b != b0) {   // boundary block: recompute serially (rare)
        float s1 = 0.f, s2 = 0.f;
        for (int i = 0; i < 192; i++) {
            s1 += part_in[((size_t)b * 192 + i) * 2];
            s2 += part_in[((size_t)b * 192 + i) * 2 + 1];
        }
        mu = s1 / (float)CHW;
        rs = rsqrtf(s2 / (float)CHW - mu * mu + EPSV);
    }
    if (!ok) return;

    const float a  = rs * gw[c];
    const float bb = gb[c] - mu * a;
    const float tau1 = tau1_p[0], vth1 = vth1_p[0];
    const float tau2 = tau2_p[0], vth2 = vth2_p[0];

    const size_t base = (size_t)(b * CH + c) * HW + (size_t)(hg * 4) * WW + wg * 4;

    float g[4][4];
#pragma unroll
    for (int i = 0; i < 4; i++) {
        float4 v = *(const float4*)(in + base + (size_t)i * WW);
        g[i][0] = gelu_f(v.x * a + bb);
        g[i][1] = gelu_f(v.y * a + bb);
        g[i][2] = gelu_f(v.z * a + bb);
        g[i][3] = gelu_f(v.w * a + bb);
    }
#pragma unroll
    for (int i = 0; i < 4; i++) {
        float u = 0.f, s = 0.f, y[4];
#pragma unroll
        for (int j = 0; j < 4; j++) {
            u = g[i][j] + tau2 * u * (1.f - s);
            s = (u > vth2) ? 1.f : 0.f;
            y[j] = u * s;
        }
        *(float4*)(xtd + base + (size_t)i * WW) = make_float4(y[0], y[1], y[2], y[3]);
    }
    float yl[4][4];
#pragma unroll
    for (int j = 0; j < 4; j++) {
        float u = 0.f, s = 0.f;
#pragma unroll
        for (int i = 0; i < 4; i++) {
            u = g[i][j] + tau1 * u * (1.f - s);
            s = (u > vth1) ? 1.f : 0.f;
            yl[i][j] = u * s;
        }
    }
#pragma unroll
    for (int i = 0; i < 4; i++)
        *(float4*)(xlr + base + (size_t)i * WW) =
            make_float4(yl[i][0], yl[i][1], yl[i][2], yl[i][3]);
}

// ---------------- host pipeline (6 launches) ---------------------------------
#define GEMM_SMEM (128 * RSTR + 256)

extern "C" void kernel_launch(void* const* d_in, const int* in_sizes, int n_in,
                              void* d_out, int out_size)
{
    const float* x    = (const float*)d_in[0];
    const float* w1   = (const float*)d_in[1];
    const float* b1   = (const float*)d_in[2];
    const float* n1w  = (const float*)d_in[3];
    const float* n1b  = (const float*)d_in[4];
    const float* dww  = (const float*)d_in[5];
    const float* dwb  = (const float*)d_in[6];
    const float* n2w  = (const float*)d_in[7];
    const float* n2b  = (const float*)d_in[8];
    const float* tau1 = (const float*)d_in[9];
    const float* vth1 = (const float*)d_in[10];
    const float* tau2 = (const float*)d_in[11];
    const float* vth2 = (const float*)d_in[12];
    const float* w21  = (const float*)d_in[13];
    const float* b21  = (const float*)d_in[14];
    const float* w22  = (const float*)d_in[15];
    const float* b22  = (const float*)d_in[16];
    const float* n3w  = (const float*)d_in[17];
    const float* n3b  = (const float*)d_in[18];
    const float* w3   = (const float*)d_in[19];
    const float* b3   = (const float*)d_in[20];
    float* out = (float*)d_out;

    float *h1, *dd, *xlr, *xtd, *tt, *p1, *p2, *p3;
    cudaGetSymbolAddress((void**)&h1,  g_h1);
    cudaGetSymbolAddress((void**)&dd,  g_d);
    cudaGetSymbolAddress((void**)&xlr, g_xlr);
    cudaGetSymbolAddress((void**)&xtd, g_xtd);
    cudaGetSymbolAddress((void**)&tt,  g_t);
    cudaGetSymbolAddress((void**)&p1,  g_p1);
    cudaGetSymbolAddress((void**)&p2,  g_p2);
    cudaGetSymbolAddress((void**)&p3,  g_p3);

    cudaFuncSetAttribute(gemm_mma<0,0,1,0>, cudaFuncAttributeMaxDynamicSharedMemorySize, GEMM_SMEM);
    cudaFuncSetAttribute(gemm_mma<0,1,0,0>, cudaFuncAttributeMaxDynamicSharedMemorySize, GEMM_SMEM);
    cudaFuncSetAttribute(gemm_mma<0,1,1,1>, cudaFuncAttributeMaxDynamicSharedMemorySize, GEMM_SMEM);
    cudaFuncSetAttribute(gemm_mma<2,0,0,0>, cudaFuncAttributeMaxDynamicSharedMemorySize, GEMM_SMEM);

    dim3 gg(25, BATCH);

    // 1. conv1 -> h1, GN1 partials
    gemm_mma<0,0,1,0><<<gg, 192, GEMM_SMEM>>>(x, w1, b1, h1, nullptr, nullptr, nullptr, p1);

    // 2. gelu(gn1(h1)) -> dwconv -> dd, GN2 partials (GN1 stats inline)
    dw_k<<<dim3(2, CH, BATCH), 256>>>(h1, p1, n1w, n1b, dww, dwb, dd, p2);

    // 3. fused LIF (GN2 stats inline)
    const int nlif = BATCH * CH * 14 * 14;
    lif_k<<<(nlif + 255) / 256, 256>>>(dd, p2, n2w, n2b, tau1, vth1, tau2, vth2, xlr, xtd);

    // 4. tt = gelu(w21@xlr+b21)
    gemm_mma<0,1,0,0><<<gg, 192, GEMM_SMEM>>>(xlr, w21, b21, tt, nullptr, nullptr, nullptr, nullptr);

    // 5. tt += gelu(w22@xtd+b22), GN3 partials
    gemm_mma<0,1,1,1><<<gg, 192, GEMM_SMEM>>>(xtd, w22, b22, tt, nullptr, nullptr, nullptr, p3);

    // 6. out = conv3 @ gn3(tt)  (GN3 stats inline)
    gemm_mma<2,0,0,0><<<gg, 192, GEMM_SMEM>>>(tt, w3, b3, out, p3, n3w, n3b, nullptr);
}

// round 8
// speedup vs baseline: 1.4721x; 1.4721x over previous
#include <cuda_runtime.h>
#include <cuda_bf16.h>
#include <math.h>
#include <stdint.h>

#define BATCH 32
#define CH    96
#define HH    56
#define WW    56
#define HW    3136
#define CHW   301056
#define TOT   9633792
#define EPSV  1e-5f

// ---------------- scratch ----------------------------------------------------
__device__ float g_h1[TOT];
__device__ float g_d [TOT];
__device__ float g_xlr[TOT];
__device__ float g_xtd[TOT];
__device__ float g_t [TOT];
__device__ float g_p1[BATCH * 25 * 2];
__device__ float g_p2[BATCH * 192 * 2];
__device__ float g_p3[BATCH * 25 * 2];

__device__ __forceinline__ float gelu_f(float x) {
    return 0.5f * x * (1.0f + erff(x * 0.7071067811865476f));
}

__device__ __forceinline__ uint32_t pack2(float lo, float hi) {
    __nv_bfloat162 t = __floats2bfloat162_rn(lo, hi);
    return *(uint32_t*)&t;
}

__device__ __forceinline__ void mma16816(float& d0, float& d1, float& d2, float& d3,
                                         uint32_t a0, uint32_t a1, uint32_t a2, uint32_t a3,
                                         uint32_t b0, uint32_t b1) {
    asm volatile(
        "mma.sync.aligned.m16n8k16.row.col.f32.bf16.bf16.f32 "
        "{%0,%1,%2,%3}, {%4,%5,%6,%7}, {%8,%9}, {%0,%1,%2,%3};"
        : "+f"(d0), "+f"(d1), "+f"(d2), "+f"(d3)
        : "r"(a0), "r"(a1), "r"(a2), "r"(a3), "r"(b0), "r"(b1));
}

// warp-0 inline GN stats from npart (sum,sumsq) pairs -> red[0]=mu, red[1]=rstd
__device__ __forceinline__ void stats_warp0(const float* __restrict__ part,
                                            int b, int npart, int warp, int lane,
                                            float* red) {
    if (warp == 0) {
        float s1 = 0.f, s2 = 0.f;
        for (int i = lane; i < npart; i += 32) {
            s1 += part[((size_t)b * npart + i) * 2];
            s2 += part[((size_t)b * npart + i) * 2 + 1];
        }
#pragma unroll
        for (int off = 16; off > 0; off >>= 1) {
            s1 += __shfl_xor_sync(0xFFFFFFFFu, s1, off);
            s2 += __shfl_xor_sync(0xFFFFFFFFu, s2, off);
        }
        if (lane == 0) {
            float mu  = s1 / (float)CHW;
            float var = s2 / (float)CHW - mu * mu;
            red[0] = mu;
            red[1] = rsqrtf(var + EPSV);
        }
    }
    __syncthreads();
}

// A-operand: weight 16x16 bf16 hi/lo fragments from global (row o_row)
__device__ __forceinline__ void load_afrags(const float* __restrict__ w, int o_row,
                                            int tig, uint32_t aH[6][4], uint32_t aL[6][4]) {
    const float* w0 = w + (size_t)o_row * CH;
#pragma unroll
    for (int s = 0; s < 6; s++) {
        const int c0 = s * 16 + 2 * tig;
#pragma unroll
        for (int q = 0; q < 4; q++) {
            const int roff = (q & 1) ? 8 * CH : 0;
            const int coff = (q & 2) ? 8 : 0;
            const float f0 = __ldg(&w0[roff + c0 + coff]);
            const float f1 = __ldg(&w0[roff + c0 + coff + 1]);
            const __nv_bfloat16 h0 = __float2bfloat16_rn(f0);
            const __nv_bfloat16 h1 = __float2bfloat16_rn(f1);
            aH[s][q] = pack2(__bfloat162float(h0), __bfloat162float(h1));
            aL[s][q] = pack2(f0 - __bfloat162float(h0), f1 - __bfloat162float(h1));
        }
    }
}

#define BSTR 104   // elements per B row (52 words; 52 ≡ 4 mod 8 -> conflict-free reads)

// ---------------- 96x96 conv1x1 (mma.sync, split-bf16) -----------------------
// INM: 2 = gn-affine input (stats inline from part_in, npart=25)
// OUTM: 1 = gelu. PART: emit partials. ACC: += existing out.
template<int INM, int OUTM, int PART, int ACC>
__global__ void __launch_bounds__(192, 3) gemm_mma(
    const float* __restrict__ in, const float* __restrict__ w,
    const float* __restrict__ bias, float* __restrict__ out,
    const float* __restrict__ part_in, const float* __restrict__ gw,
    const float* __restrict__ gb, float* __restrict__ part)
{
    extern __shared__ char dsm[];
    __nv_bfloat16* bhm = (__nv_bfloat16*)dsm;            // [128][104] hi
    __nv_bfloat16* blm = bhm + 128 * BSTR;               // [128][104] lo
    uint32_t* bh32 = (uint32_t*)bhm;
    uint32_t* bl32 = (uint32_t*)blm;
    float* red = (float*)(dsm + 128 * BSTR * 2 * 2);

    const int b    = blockIdx.y;
    const int p0   = blockIdx.x * 128;
    const int tid  = threadIdx.x;
    const int warp = tid >> 5, lane = tid & 31;
    const int gid  = lane >> 2, tig = lane & 3;
    const int o0   = warp * 16;

    float mu = 0.f, rs = 0.f;
    if (INM == 2) {
        stats_warp0(part_in, b, 25, warp, lane, red);
        mu = red[0]; rs = red[1];
        __syncthreads();
    }

    // ---- B fill: (c,c+1) pair-packed, one STS.32 per buffer ---------------
    const float* inb = in + (size_t)b * CHW + p0;
    for (int i = tid; i < 48 * 128; i += 192) {
        const int px = i & 127, cp = i >> 7;      // cp = c/2, 0..47
        const int c = cp * 2;
        float v0 = 0.f, v1 = 0.f;
        if (p0 + px < HW) {
            v0 = inb[(size_t)c * HW + px];
            v1 = inb[(size_t)(c + 1) * HW + px];
        }
        if (INM == 2) {
            float a0 = rs * gw[c],     bb0 = gb[c]     - mu * a0;
            float a1 = rs * gw[c + 1], bb1 = gb[c + 1] - mu * a1;
            v0 = v0 * a0 + bb0;
            v1 = v1 * a1 + bb1;
        }
        const __nv_bfloat16 h0 = __float2bfloat16_rn(v0);
        const __nv_bfloat16 h1 = __float2bfloat16_rn(v1);
        const float l0 = v0 - __bfloat162float(h0);
        const float l1 = v1 - __bfloat162float(h1);
        const int wi = px * 52 + cp;
        bh32[wi] = pack2(__bfloat162float(h0), __bfloat162float(h1));
        bl32[wi] = pack2(l0, l1);
    }

    uint32_t aH[6][4], aL[6][4];
    load_afrags(w, o0 + gid, tig, aH, aL);
    __syncthreads();

    const float bias0 = bias[o0 + gid];
    const float bias1 = bias[o0 + gid + 8];
    float s1 = 0.f, s2 = 0.f;
    float* ob = out + (size_t)b * CHW;

    for (int nt = 0; nt < 16; nt++) {
        float d0 = 0.f, d1 = 0.f, d2 = 0.f, d3 = 0.f;
        const __nv_bfloat16* bhp = bhm + (nt * 8 + gid) * BSTR + 2 * tig;
        const __nv_bfloat16* blp = blm + (nt * 8 + gid) * BSTR + 2 * tig;
#pragma unroll
        for (int s = 0; s < 6; s++) {
            const uint32_t bh0 = *(const uint32_t*)(bhp + 16 * s);
            const uint32_t bh1 = *(const uint32_t*)(bhp + 16 * s + 8);
            const uint32_t bl0 = *(const uint32_t*)(blp + 16 * s);
            const uint32_t bl1 = *(const uint32_t*)(blp + 16 * s + 8);
            mma16816(d0, d1, d2, d3, aH[s][0], aH[s][1], aH[s][2], aH[s][3], bh0, bh1);
            mma16816(d0, d1, d2, d3, aL[s][0], aL[s][1], aL[s][2], aL[s][3], bh0, bh1);
            mma16816(d0, d1, d2, d3, aH[s][0], aH[s][1], aH[s][2], aH[s][3], bl0, bl1);
        }
        const int px = p0 + nt * 8 + 2 * tig;
        if (px < HW) {
            float v00 = d0 + bias0, v01 = d1 + bias0;
            float v10 = d2 + bias1, v11 = d3 + bias1;
            if (OUTM == 1) {
                v00 = gelu_f(v00); v01 = gelu_f(v01);
                v10 = gelu_f(v10); v11 = gelu_f(v11);
            }
            float* p00 = ob + (size_t)(o0 + gid) * HW + px;
            float* p10 = ob + (size_t)(o0 + gid + 8) * HW + px;
            if (ACC) {
                float2 t0 = *(float2*)p00; v00 += t0.x; v01 += t0.y;
                float2 t1 = *(float2*)p10; v10 += t1.x; v11 += t1.y;
            }
            *(float2*)p00 = make_float2(v00, v01);
            *(float2*)p10 = make_float2(v10, v11);
            if (PART) {
                s1 += v00 + v01 + v10 + v11;
                s2 += v00 * v00 + v01 * v01 + v10 * v10 + v11 * v11;
            }
        }
    }

    if (PART) {
#pragma unroll
        for (int off = 16; off > 0; off >>= 1) {
            s1 += __shfl_xor_sync(0xFFFFFFFFu, s1, off);
            s2 += __shfl_xor_sync(0xFFFFFFFFu, s2, off);
        }
        __syncthreads();
        if (lane == 0) { red[warp] = s1; red[8 + warp] = s2; }
        __syncthreads();
        if (tid == 0) {
            float t1 = 0.f, t2 = 0.f;
#pragma unroll
            for (int i = 0; i < 6; i++) { t1 += red[i]; t2 += red[8 + i]; }
            float* pp = part + ((size_t)b * gridDim.x + blockIdx.x) * 2;
            pp[0] = t1; pp[1] = t2;
        }
    }
}

// ---------------- depthwise 3x3, fused GN1+GELU (stats inline) ---------------
__global__ void __launch_bounds__(256) dw_k(
    const float* __restrict__ in, const float* __restrict__ part_in,
    const float* __restrict__ gw, const float* __restrict__ gb,
    const float* __restrict__ dww, const float* __restrict__ dwb,
    float* __restrict__ out, float* __restrict__ part)
{
    __shared__ float tile[30][58];
    __shared__ float red[512];
    const int rt = blockIdx.x;
    const int c  = blockIdx.y;
    const int b  = blockIdx.z;
    const int tid = threadIdx.x;
    const int warp = tid >> 5, lane = tid & 31;

    stats_warp0(part_in, b, 25, warp, lane, red);
    const float mu = red[0], rs = red[1];
    __syncthreads();

    const float a  = rs * gw[c];
    const float bb = gb[c] - mu * a;
    const float* inb = in + (size_t)(b * CH + c) * HW;
    const int r0 = rt * 28;

    for (int i = tid; i < 30 * 58; i += 256) {
        int rr = i / 58, cc = i % 58;
        int gr = r0 - 1 + rr, gc = cc - 1;
        float v = 0.f;
        if (gr >= 0 && gr < HH && gc >= 0 && gc < WW)
            v = gelu_f(inb[gr * WW + gc] * a + bb);
        tile[rr][cc] = v;
    }
    float wd[9];
#pragma unroll
    for (int i = 0; i < 9; i++) wd[i] = dww[c * 9 + i];
    const float bd = dwb[c];
    __syncthreads();

    float s1 = 0.f, s2 = 0.f;
    for (int p = tid; p < 28 * 56; p += 256) {
        int lr = p / 56, lc = p % 56;
        float accv = bd;
#pragma unroll
        for (int i = 0; i < 3; i++)
#pragma unroll
            for (int j = 0; j < 3; j++)
                accv = fmaf(wd[i * 3 + j], tile[lr + i][lc + j], accv);
        out[(size_t)(b * CH + c) * HW + (r0 + lr) * WW + lc] = accv;
        s1 += accv; s2 += accv * accv;
    }
    red[tid] = s1; red[256 + tid] = s2;
    __syncthreads();
    for (int off = 128; off > 0; off >>= 1) {
        if (tid < off) {
            red[tid] += red[tid + off];
            red[256 + tid] += red[256 + tid + off];
        }
        __syncthreads();
    }
    if (tid == 0) {
        float* pp = part + ((size_t)b * 192 + c * 2 + rt) * 2;
        pp[0] = red[0]; pp[1] = red[256];
    }
}

// ---------------- fused LIF (stats inline, H and W scans, 4x4 tile) ----------
__global__ void __launch_bounds__(256) lif_k(
    const float* __restrict__ in, const float* __restrict__ part_in,
    const float* __restrict__ gw, const float* __restrict__ gb,
    const float* __restrict__ tau1_p, const float* __restrict__ vth1_p,
    const float* __restrict__ tau2_p, const float* __restrict__ vth2_p,
    float* __restrict__ xlr, float* __restrict__ xtd)
{
    __shared__ float red[2];
    const int tid = threadIdx.x;
    const int warp = tid >> 5, lane = tid & 31;
    const int idx = blockIdx.x * 256 + tid;

    const int wg = idx % 14;
    const int hg = (idx / 14) % 14;
    const int c  = (idx / 196) % CH;
    const int b  = idx / (196 * CH);
    const bool ok = idx < BATCH * CH * 14 * 14;

    const int b0 = (blockIdx.x * 256) / 18816;
    if (warp == 0) {
        float s1 = 0.f, s2 = 0.f;
        for (int i = lane; i < 192; i += 32) {
            s1 += part_in[((size_t)b0 * 192 + i) * 2];
            s2 += part_in[((size_t)b0 * 192 + i) * 2 + 1];
        }
#pragma unroll
        for (int off = 16; off > 0; off >>= 1) {
            s1 += __shfl_xor_sync(0xFFFFFFFFu, s1, off);
            s2 += __shfl_xor_sync(0xFFFFFFFFu, s2, off);
        }
        if (lane == 0) {
            float m = s1 / (float)CHW;
            red[0] = m;
            red[1] = rsqrtf(s2 / (float)CHW - m * m + EPSV);
        }
    }
    __syncthreads();
    float mu = red[0], rs = red[1];
    if (ok && b != b0) {   // boundary block: recompute serially (rare)
        float s1 = 0.f, s2 = 0.f;
        for (int i = 0; i < 192; i++) {
            s1 += part_in[((size_t)b * 192 + i) * 2];
            s2 += part_in[((size_t)b * 192 + i) * 2 + 1];
        }
        mu = s1 / (float)CHW;
        rs = rsqrtf(s2 / (float)CHW - mu * mu + EPSV);
    }
    if (!ok) return;

    const float a  = rs * gw[c];
    const float bb = gb[c] - mu * a;
    const float tau1 = tau1_p[0], vth1 = vth1_p[0];
    const float tau2 = tau2_p[0], vth2 = vth2_p[0];

    const size_t base = (size_t)(b * CH + c) * HW + (size_t)(hg * 4) * WW + wg * 4;

    float g[4][4];
#pragma unroll
    for (int i = 0; i < 4; i++) {
        float4 v = *(const float4*)(in + base + (size_t)i * WW);
        g[i][0] = gelu_f(v.x * a + bb);
        g[i][1] = gelu_f(v.y * a + bb);
        g[i][2] = gelu_f(v.z * a + bb);
        g[i][3] = gelu_f(v.w * a + bb);
    }
#pragma unroll
    for (int i = 0; i < 4; i++) {
        float u = 0.f, s = 0.f, y[4];
#pragma unroll
        for (int j = 0; j < 4; j++) {
            u = g[i][j] + tau2 * u * (1.f - s);
            s = (u > vth2) ? 1.f : 0.f;
            y[j] = u * s;
        }
        *(float4*)(xtd + base + (size_t)i * WW) = make_float4(y[0], y[1], y[2], y[3]);
    }
    float yl[4][4];
#pragma unroll
    for (int j = 0; j < 4; j++) {
        float u = 0.f, s = 0.f;
#pragma unroll
        for (int i = 0; i < 4; i++) {
            u = g[i][j] + tau1 * u * (1.f - s);
            s = (u > vth1) ? 1.f : 0.f;
            yl[i][j] = u * s;
        }
    }
#pragma unroll
    for (int i = 0; i < 4; i++)
        *(float4*)(xlr + base + (size_t)i * WW) =
            make_float4(yl[i][0], yl[i][1], yl[i][2], yl[i][3]);
}

// ---------------- host pipeline (6 launches) ---------------------------------
#define GEMM_SMEM (128 * BSTR * 2 * 2 + 256)

extern "C" void kernel_launch(void* const* d_in, const int* in_sizes, int n_in,
                              void* d_out, int out_size)
{
    const float* x    = (const float*)d_in[0];
    const float* w1   = (const float*)d_in[1];
    const float* b1   = (const float*)d_in[2];
    const float* n1w  = (const float*)d_in[3];
    const float* n1b  = (const float*)d_in[4];
    const float* dww  = (const float*)d_in[5];
    const float* dwb  = (const float*)d_in[6];
    const float* n2w  = (const float*)d_in[7];
    const float* n2b  = (const float*)d_in[8];
    const float* tau1 = (const float*)d_in[9];
    const float* vth1 = (const float*)d_in[10];
    const float* tau2 = (const float*)d_in[11];
    const float* vth2 = (const float*)d_in[12];
    const float* w21  = (const float*)d_in[13];
    const float* b21  = (const float*)d_in[14];
    const float* w22  = (const float*)d_in[15];
    const float* b22  = (const float*)d_in[16];
    const float* n3w  = (const float*)d_in[17];
    const float* n3b  = (const float*)d_in[18];
    const float* w3   = (const float*)d_in[19];
    const float* b3   = (const float*)d_in[20];
    float* out = (float*)d_out;

    float *h1, *dd, *xlr, *xtd, *tt, *p1, *p2, *p3;
    cudaGetSymbolAddress((void**)&h1,  g_h1);
    cudaGetSymbolAddress((void**)&dd,  g_d);
    cudaGetSymbolAddress((void**)&xlr, g_xlr);
    cudaGetSymbolAddress((void**)&xtd, g_xtd);
    cudaGetSymbolAddress((void**)&tt,  g_t);
    cudaGetSymbolAddress((void**)&p1,  g_p1);
    cudaGetSymbolAddress((void**)&p2,  g_p2);
    cudaGetSymbolAddress((void**)&p3,  g_p3);

    cudaFuncSetAttribute(gemm_mma<0,0,1,0>, cudaFuncAttributeMaxDynamicSharedMemorySize, GEMM_SMEM);
    cudaFuncSetAttribute(gemm_mma<0,1,0,0>, cudaFuncAttributeMaxDynamicSharedMemorySize, GEMM_SMEM);
    cudaFuncSetAttribute(gemm_mma<0,1,1,1>, cudaFuncAttributeMaxDynamicSharedMemorySize, GEMM_SMEM);
    cudaFuncSetAttribute(gemm_mma<2,0,0,0>, cudaFuncAttributeMaxDynamicSharedMemorySize, GEMM_SMEM);

    dim3 gg(25, BATCH);

    // 1. conv1 -> h1, GN1 partials
    gemm_mma<0,0,1,0><<<gg, 192, GEMM_SMEM>>>(x, w1, b1, h1, nullptr, nullptr, nullptr, p1);

    // 2. gelu(gn1(h1)) -> dwconv -> dd, GN2 partials (GN1 stats inline)
    dw_k<<<dim3(2, CH, BATCH), 256>>>(h1, p1, n1w, n1b, dww, dwb, dd, p2);

    // 3. fused LIF (GN2 stats inline)
    const int nlif = BATCH * CH * 14 * 14;
    lif_k<<<(nlif + 255) / 256, 256>>>(dd, p2, n2w, n2b, tau1, vth1, tau2, vth2, xlr, xtd);

    // 4. tt = gelu(w21@xlr+b21)
    gemm_mma<0,1,0,0><<<gg, 192, GEMM_SMEM>>>(xlr, w21, b21, tt, nullptr, nullptr, nullptr, nullptr);

    // 5. tt += gelu(w22@xtd+b22), GN3 partials
    gemm_mma<0,1,1,1><<<gg, 192, GEMM_SMEM>>>(xtd, w22, b22, tt, nullptr, nullptr, nullptr, p3);

    // 6. out = conv3 @ gn3(tt)  (GN3 stats inline)
    gemm_mma<2,0,0,0><<<gg, 192, GEMM_SMEM>>>(tt, w3, b3, out, p3, n3w, n3b, nullptr);
}

// round 9
// speedup vs baseline: 1.4903x; 1.0123x over previous
#include <cuda_runtime.h>
#include <cuda_bf16.h>
#include <math.h>
#include <stdint.h>

#define BATCH 32
#define CH    96
#define HH    56
#define WW    56
#define HW    3136
#define CHW   301056
#define TOT   9633792
#define EPSV  1e-5f

// ---------------- scratch ----------------------------------------------------
__device__ float g_h1[TOT];
__device__ float g_d [TOT];
__device__ float g_xlr[TOT];
__device__ float g_xtd[TOT];
__device__ float g_t [TOT];
__device__ float g_p1[BATCH * 25 * 2];
__device__ float g_p2[BATCH * 192 * 2];
__device__ float g_p3[BATCH * 25 * 2];

__device__ __forceinline__ float gelu_f(float x) {
    return 0.5f * x * (1.0f + erff(x * 0.7071067811865476f));
}

__device__ __forceinline__ uint32_t pack2(float lo, float hi) {
    __nv_bfloat162 t = __floats2bfloat162_rn(lo, hi);
    return *(uint32_t*)&t;
}

__device__ __forceinline__ void mma16816(float& d0, float& d1, float& d2, float& d3,
                                         uint32_t a0, uint32_t a1, uint32_t a2, uint32_t a3,
                                         uint32_t b0, uint32_t b1) {
    asm volatile(
        "mma.sync.aligned.m16n8k16.row.col.f32.bf16.bf16.f32 "
        "{%0,%1,%2,%3}, {%4,%5,%6,%7}, {%8,%9}, {%0,%1,%2,%3};"
        : "+f"(d0), "+f"(d1), "+f"(d2), "+f"(d3)
        : "r"(a0), "r"(a1), "r"(a2), "r"(a3), "r"(b0), "r"(b1));
}

__device__ __forceinline__ void ldsm_x4(uint32_t& r0, uint32_t& r1,
                                        uint32_t& r2, uint32_t& r3, uint32_t addr) {
    asm volatile("ldmatrix.sync.aligned.m8n8.x4.shared.b16 {%0,%1,%2,%3}, [%4];"
                 : "=r"(r0), "=r"(r1), "=r"(r2), "=r"(r3) : "r"(addr));
}

__device__ __forceinline__ uint32_t smem_addr(const void* p) {
    return (uint32_t)__cvta_generic_to_shared(p);
}

// warp-0 inline GN stats from npart (sum,sumsq) pairs -> red[0]=mu, red[1]=rstd
__device__ __forceinline__ void stats_warp0(const float* __restrict__ part,
                                            int b, int npart, int warp, int lane,
                                            float* red) {
    if (warp == 0) {
        float s1 = 0.f, s2 = 0.f;
        for (int i = lane; i < npart; i += 32) {
            s1 += part[((size_t)b * npart + i) * 2];
            s2 += part[((size_t)b * npart + i) * 2 + 1];
        }
#pragma unroll
        for (int off = 16; off > 0; off >>= 1) {
            s1 += __shfl_xor_sync(0xFFFFFFFFu, s1, off);
            s2 += __shfl_xor_sync(0xFFFFFFFFu, s2, off);
        }
        if (lane == 0) {
            float mu  = s1 / (float)CHW;
            float var = s2 / (float)CHW - mu * mu;
            red[0] = mu;
            red[1] = rsqrtf(var + EPSV);
        }
    }
    __syncthreads();
}

// A-operand: weight 16x16 bf16 hi/lo fragments from global (row o_row)
__device__ __forceinline__ void load_afrags(const float* __restrict__ w, int o_row,
                                            int tig, uint32_t aH[6][4], uint32_t aL[6][4]) {
    const float* w0 = w + (size_t)o_row * CH;
#pragma unroll
    for (int s = 0; s < 6; s++) {
        const int c0 = s * 16 + 2 * tig;
#pragma unroll
        for (int q = 0; q < 4; q++) {
            const int roff = (q & 1) ? 8 * CH : 0;
            const int coff = (q & 2) ? 8 : 0;
            const float f0 = __ldg(&w0[roff + c0 + coff]);
            const float f1 = __ldg(&w0[roff + c0 + coff + 1]);
            const __nv_bfloat16 h0 = __float2bfloat16_rn(f0);
            const __nv_bfloat16 h1 = __float2bfloat16_rn(f1);
            aH[s][q] = pack2(__bfloat162float(h0), __bfloat162float(h1));
            aL[s][q] = pack2(f0 - __bfloat162float(h0), f1 - __bfloat162float(h1));
        }
    }
}

#define BSTR 104   // elements per B row (52 words; conflict-free ldmatrix phases)

// ---------------- 96x96 conv1x1 (mma.sync, split-bf16, ldmatrix B) -----------
// INM: 2 = gn-affine input (stats inline from part_in, npart=25)
// OUTM: 1 = gelu. PART: emit partials. ACC: += existing out.
template<int INM, int OUTM, int PART, int ACC>
__global__ void __launch_bounds__(192, 3) gemm_mma(
    const float* __restrict__ in, const float* __restrict__ w,
    const float* __restrict__ bias, float* __restrict__ out,
    const float* __restrict__ part_in, const float* __restrict__ gw,
    const float* __restrict__ gb, float* __restrict__ part)
{
    extern __shared__ char dsm[];
    __nv_bfloat16* bhm = (__nv_bfloat16*)dsm;            // [128][104] hi
    __nv_bfloat16* blm = bhm + 128 * BSTR;               // [128][104] lo
    uint32_t* bh32 = (uint32_t*)bhm;
    uint32_t* bl32 = (uint32_t*)blm;
    float* red = (float*)(dsm + 128 * BSTR * 2 * 2);

    const int b    = blockIdx.y;
    const int p0   = blockIdx.x * 128;
    const int tid  = threadIdx.x;
    const int warp = tid >> 5, lane = tid & 31;
    const int gid  = lane >> 2, tig = lane & 3;
    const int o0   = warp * 16;

    float mu = 0.f, rs = 0.f;
    if (INM == 2) {
        stats_warp0(part_in, b, 25, warp, lane, red);
        mu = red[0]; rs = red[1];
        __syncthreads();
    }

    // ---- B fill: (c,c+1) pair-packed, one STS.32 per buffer ---------------
    const float* inb = in + (size_t)b * CHW + p0;
    for (int i = tid; i < 48 * 128; i += 192) {
        const int px = i & 127, cp = i >> 7;
        const int c = cp * 2;
        float v0 = 0.f, v1 = 0.f;
        if (p0 + px < HW) {
            v0 = inb[(size_t)c * HW + px];
            v1 = inb[(size_t)(c + 1) * HW + px];
        }
        if (INM == 2) {
            float a0 = rs * gw[c],     bb0 = gb[c]     - mu * a0;
            float a1 = rs * gw[c + 1], bb1 = gb[c + 1] - mu * a1;
            v0 = v0 * a0 + bb0;
            v1 = v1 * a1 + bb1;
        }
        const __nv_bfloat16 h0 = __float2bfloat16_rn(v0);
        const __nv_bfloat16 h1 = __float2bfloat16_rn(v1);
        const float l0 = v0 - __bfloat162float(h0);
        const float l1 = v1 - __bfloat162float(h1);
        const int wi = px * 52 + cp;
        bh32[wi] = pack2(__bfloat162float(h0), __bfloat162float(h1));
        bl32[wi] = pack2(l0, l1);
    }

    uint32_t aH[6][4], aL[6][4];
    load_afrags(w, o0 + gid, tig, aH, aL);
    __syncthreads();

    // ldmatrix lane pointers: lane L -> matrix mL = L>>3, row rL = L&7.
    // group g covers s-pair (2g, 2g+1): k-offset = (2g + (mL>>1))*16 + (mL&1)*8
    const int rL = lane & 7, mL = lane >> 3;
    uint32_t hadr[3], ladr[3];
#pragma unroll
    for (int g = 0; g < 3; g++) {
        const uint32_t eoff = (uint32_t)(rL * BSTR + (2 * g + (mL >> 1)) * 16 + (mL & 1) * 8);
        hadr[g] = smem_addr(bhm + eoff);
        ladr[g] = smem_addr(blm + eoff);
    }
    const uint32_t ntstep = 8 * BSTR * 2;   // bytes per nt-tile of 8 px rows

    const float bias0 = bias[o0 + gid];
    const float bias1 = bias[o0 + gid + 8];
    float s1 = 0.f, s2 = 0.f;
    float* ob = out + (size_t)b * CHW;

    for (int nt = 0; nt < 16; nt++) {
        float d0 = 0.f, d1 = 0.f, d2 = 0.f, d3 = 0.f;
        uint32_t bh[12], bl[12];
#pragma unroll
        for (int g = 0; g < 3; g++) {
            ldsm_x4(bh[4 * g], bh[4 * g + 1], bh[4 * g + 2], bh[4 * g + 3], hadr[g]);
            ldsm_x4(bl[4 * g], bl[4 * g + 1], bl[4 * g + 2], bl[4 * g + 3], ladr[g]);
            hadr[g] += ntstep;
            ladr[g] += ntstep;
        }
#pragma unroll
        for (int s = 0; s < 6; s++) {
            const uint32_t bh0 = bh[2 * s], bh1 = bh[2 * s + 1];
            const uint32_t bl0 = bl[2 * s], bl1 = bl[2 * s + 1];
            mma16816(d0, d1, d2, d3, aH[s][0], aH[s][1], aH[s][2], aH[s][3], bh0, bh1);
            mma16816(d0, d1, d2, d3, aL[s][0], aL[s][1], aL[s][2], aL[s][3], bh0, bh1);
            mma16816(d0, d1, d2, d3, aH[s][0], aH[s][1], aH[s][2], aH[s][3], bl0, bl1);
        }
        const int px = p0 + nt * 8 + 2 * tig;
        if (px < HW) {
            float v00 = d0 + bias0, v01 = d1 + bias0;
            float v10 = d2 + bias1, v11 = d3 + bias1;
            if (OUTM == 1) {
                v00 = gelu_f(v00); v01 = gelu_f(v01);
                v10 = gelu_f(v10); v11 = gelu_f(v11);
            }
            float* p00 = ob + (size_t)(o0 + gid) * HW + px;
            float* p10 = ob + (size_t)(o0 + gid + 8) * HW + px;
            if (ACC) {
                float2 t0 = *(float2*)p00; v00 += t0.x; v01 += t0.y;
                float2 t1 = *(float2*)p10; v10 += t1.x; v11 += t1.y;
            }
            *(float2*)p00 = make_float2(v00, v01);
            *(float2*)p10 = make_float2(v10, v11);
            if (PART) {
                s1 += v00 + v01 + v10 + v11;
                s2 += v00 * v00 + v01 * v01 + v10 * v10 + v11 * v11;
            }
        }
    }

    if (PART) {
#pragma unroll
        for (int off = 16; off > 0; off >>= 1) {
            s1 += __shfl_xor_sync(0xFFFFFFFFu, s1, off);
            s2 += __shfl_xor_sync(0xFFFFFFFFu, s2, off);
        }
        __syncthreads();
        if (lane == 0) { red[warp] = s1; red[8 + warp] = s2; }
        __syncthreads();
        if (tid == 0) {
            float t1 = 0.f, t2 = 0.f;
#pragma unroll
            for (int i = 0; i < 6; i++) { t1 += red[i]; t2 += red[8 + i]; }
            float* pp = part + ((size_t)b * gridDim.x + blockIdx.x) * 2;
            pp[0] = t1; pp[1] = t2;
        }
    }
}

// ---------------- depthwise 3x3, fused GN1+GELU (stats inline) ---------------
__global__ void __launch_bounds__(256) dw_k(
    const float* __restrict__ in, const float* __restrict__ part_in,
    const float* __restrict__ gw, const float* __restrict__ gb,
    const float* __restrict__ dww, const float* __restrict__ dwb,
    float* __restrict__ out, float* __restrict__ part)
{
    __shared__ float tile[30][58];
    __shared__ float red[512];
    const int rt = blockIdx.x;
    const int c  = blockIdx.y;
    const int b  = blockIdx.z;
    const int tid = threadIdx.x;
    const int warp = tid >> 5, lane = tid & 31;

    stats_warp0(part_in, b, 25, warp, lane, red);
    const float mu = red[0], rs = red[1];
    __syncthreads();

    const float a  = rs * gw[c];
    const float bb = gb[c] - mu * a;
    const float* inb = in + (size_t)(b * CH + c) * HW;
    const int r0 = rt * 28;

    for (int i = tid; i < 30 * 58; i += 256) {
        int rr = i / 58, cc = i % 58;
        int gr = r0 - 1 + rr, gc = cc - 1;
        float v = 0.f;
        if (gr >= 0 && gr < HH && gc >= 0 && gc < WW)
            v = gelu_f(inb[gr * WW + gc] * a + bb);
        tile[rr][cc] = v;
    }
    float wd[9];
#pragma unroll
    for (int i = 0; i < 9; i++) wd[i] = dww[c * 9 + i];
    const float bd = dwb[c];
    __syncthreads();

    float s1 = 0.f, s2 = 0.f;
    for (int p = tid; p < 28 * 56; p += 256) {
        int lr = p / 56, lc = p % 56;
        float accv = bd;
#pragma unroll
        for (int i = 0; i < 3; i++)
#pragma unroll
            for (int j = 0; j < 3; j++)
                accv = fmaf(wd[i * 3 + j], tile[lr + i][lc + j], accv);
        out[(size_t)(b * CH + c) * HW + (r0 + lr) * WW + lc] = accv;
        s1 += accv; s2 += accv * accv;
    }
    red[tid] = s1; red[256 + tid] = s2;
    __syncthreads();
    for (int off = 128; off > 0; off >>= 1) {
        if (tid < off) {
            red[tid] += red[tid + off];
            red[256 + tid] += red[256 + tid + off];
        }
        __syncthreads();
    }
    if (tid == 0) {
        float* pp = part + ((size_t)b * 192 + c * 2 + rt) * 2;
        pp[0] = red[0]; pp[1] = red[256];
    }
}

// ---------------- fused LIF (stats inline, H and W scans, 4x4 tile) ----------
__global__ void __launch_bounds__(256) lif_k(
    const float* __restrict__ in, const float* __restrict__ part_in,
    const float* __restrict__ gw, const float* __restrict__ gb,
    const float* __restrict__ tau1_p, const float* __restrict__ vth1_p,
    const float* __restrict__ tau2_p, const float* __restrict__ vth2_p,
    float* __restrict__ xlr, float* __restrict__ xtd)
{
    __shared__ float red[2];
    const int tid = threadIdx.x;
    const int warp = tid >> 5, lane = tid & 31;
    const int idx = blockIdx.x * 256 + tid;

    const int wg = idx % 14;
    const int hg = (idx / 14) % 14;
    const int c  = (idx / 196) % CH;
    const int b  = idx / (196 * CH);
    const bool ok = idx < BATCH * CH * 14 * 14;

    const int b0 = (blockIdx.x * 256) / 18816;
    if (warp == 0) {
        float s1 = 0.f, s2 = 0.f;
        for (int i = lane; i < 192; i += 32) {
            s1 += part_in[((size_t)b0 * 192 + i) * 2];
            s2 += part_in[((size_t)b0 * 192 + i) * 2 + 1];
        }
#pragma unroll
        for (int off = 16; off > 0; off >>= 1) {
            s1 += __shfl_xor_sync(0xFFFFFFFFu, s1, off);
            s2 += __shfl_xor_sync(0xFFFFFFFFu, s2, off);
        }
        if (lane == 0) {
            float m = s1 / (float)CHW;
            red[0] = m;
            red[1] = rsqrtf(s2 / (float)CHW - m * m + EPSV);
        }
    }
    __syncthreads();
    float mu = red[0], rs = red[1];
    if (ok && b != b0) {   // boundary block: recompute serially (rare)
        float s1 = 0.f, s2 = 0.f;
        for (int i = 0; i < 192; i++) {
            s1 += part_in[((size_t)b * 192 + i) * 2];
            s2 += part_in[((size_t)b * 192 + i) * 2 + 1];
        }
        mu = s1 / (float)CHW;
        rs = rsqrtf(s2 / (float)CHW - mu * mu + EPSV);
    }
    if (!ok) return;

    const float a  = rs * gw[c];
    const float bb = gb[c] - mu * a;
    const float tau1 = tau1_p[0], vth1 = vth1_p[0];
    const float tau2 = tau2_p[0], vth2 = vth2_p[0];

    const size_t base = (size_t)(b * CH + c) * HW + (size_t)(hg * 4) * WW + wg * 4;

    float g[4][4];
#pragma unroll
    for (int i = 0; i < 4; i++) {
        float4 v = *(const float4*)(in + base + (size_t)i * WW);
        g[i][0] = gelu_f(v.x * a + bb);
        g[i][1] = gelu_f(v.y * a + bb);
        g[i][2] = gelu_f(v.z * a + bb);
        g[i][3] = gelu_f(v.w * a + bb);
    }
#pragma unroll
    for (int i = 0; i < 4; i++) {
        float u = 0.f, s = 0.f, y[4];
#pragma unroll
        for (int j = 0; j < 4; j++) {
            u = g[i][j] + tau2 * u * (1.f - s);
            s = (u > vth2) ? 1.f : 0.f;
            y[j] = u * s;
        }
        *(float4*)(xtd + base + (size_t)i * WW) = make_float4(y[0], y[1], y[2], y[3]);
    }
    float yl[4][4];
#pragma unroll
    for (int j = 0; j < 4; j++) {
        float u = 0.f, s = 0.f;
#pragma unroll
        for (int i = 0; i < 4; i++) {
            u = g[i][j] + tau1 * u * (1.f - s);
            s = (u > vth1) ? 1.f : 0.f;
            yl[i][j] = u * s;
        }
    }
#pragma unroll
    for (int i = 0; i < 4; i++)
        *(float4*)(xlr + base + (size_t)i * WW) =
            make_float4(yl[i][0], yl[i][1], yl[i][2], yl[i][3]);
}

// ---------------- host pipeline (6 launches) ---------------------------------
#define GEMM_SMEM (128 * BSTR * 2 * 2 + 256)

extern "C" void kernel_launch(void* const* d_in, const int* in_sizes, int n_in,
                              void* d_out, int out_size)
{
    const float* x    = (const float*)d_in[0];
    const float* w1   = (const float*)d_in[1];
    const float* b1   = (const float*)d_in[2];
    const float* n1w  = (const float*)d_in[3];
    const float* n1b  = (const float*)d_in[4];
    const float* dww  = (const float*)d_in[5];
    const float* dwb  = (const float*)d_in[6];
    const float* n2w  = (const float*)d_in[7];
    const float* n2b  = (const float*)d_in[8];
    const float* tau1 = (const float*)d_in[9];
    const float* vth1 = (const float*)d_in[10];
    const float* tau2 = (const float*)d_in[11];
    const float* vth2 = (const float*)d_in[12];
    const float* w21  = (const float*)d_in[13];
    const float* b21  = (const float*)d_in[14];
    const float* w22  = (const float*)d_in[15];
    const float* b22  = (const float*)d_in[16];
    const float* n3w  = (const float*)d_in[17];
    const float* n3b  = (const float*)d_in[18];
    const float* w3   = (const float*)d_in[19];
    const float* b3   = (const float*)d_in[20];
    float* out = (float*)d_out;

    float *h1, *dd, *xlr, *xtd, *tt, *p1, *p2, *p3;
    cudaGetSymbolAddress((void**)&h1,  g_h1);
    cudaGetSymbolAddress((void**)&dd,  g_d);
    cudaGetSymbolAddress((void**)&xlr, g_xlr);
    cudaGetSymbolAddress((void**)&xtd, g_xtd);
    cudaGetSymbolAddress((void**)&tt,  g_t);
    cudaGetSymbolAddress((void**)&p1,  g_p1);
    cudaGetSymbolAddress((void**)&p2,  g_p2);
    cudaGetSymbolAddress((void**)&p3,  g_p3);

    cudaFuncSetAttribute(gemm_mma<0,0,1,0>, cudaFuncAttributeMaxDynamicSharedMemorySize, GEMM_SMEM);
    cudaFuncSetAttribute(gemm_mma<0,1,0,0>, cudaFuncAttributeMaxDynamicSharedMemorySize, GEMM_SMEM);
    cudaFuncSetAttribute(gemm_mma<0,1,1,1>, cudaFuncAttributeMaxDynamicSharedMemorySize, GEMM_SMEM);
    cudaFuncSetAttribute(gemm_mma<2,0,0,0>, cudaFuncAttributeMaxDynamicSharedMemorySize, GEMM_SMEM);

    dim3 gg(25, BATCH);

    // 1. conv1 -> h1, GN1 partials
    gemm_mma<0,0,1,0><<<gg, 192, GEMM_SMEM>>>(x, w1, b1, h1, nullptr, nullptr, nullptr, p1);

    // 2. gelu(gn1(h1)) -> dwconv -> dd, GN2 partials (GN1 stats inline)
    dw_k<<<dim3(2, CH, BATCH), 256>>>(h1, p1, n1w, n1b, dww, dwb, dd, p2);

    // 3. fused LIF (GN2 stats inline)
    const int nlif = BATCH * CH * 14 * 14;
    lif_k<<<(nlif + 255) / 256, 256>>>(dd, p2, n2w, n2b, tau1, vth1, tau2, vth2, xlr, xtd);

    // 4. tt = gelu(w21@xlr+b21)
    gemm_mma<0,1,0,0><<<gg, 192, GEMM_SMEM>>>(xlr, w21, b21, tt, nullptr, nullptr, nullptr, nullptr);

    // 5. tt += gelu(w22@xtd+b22), GN3 partials
    gemm_mma<0,1,1,1><<<gg, 192, GEMM_SMEM>>>(xtd, w22, b22, tt, nullptr, nullptr, nullptr, p3);

    // 6. out = conv3 @ gn3(tt)  (GN3 stats inline)
    gemm_mma<2,0,0,0><<<gg, 192, GEMM_SMEM>>>(tt, w3, b3, out, p3, n3w, n3b, nullptr);
}

// round 10
// speedup vs baseline: 1.5390x; 1.0327x over previous
#include <cuda_runtime.h>
#include <cuda_bf16.h>
#include <math.h>
#include <stdint.h>

#define BATCH 32
#define CH    96
#define HH    56
#define WW    56
#define HW    3136
#define CHW   301056
#define TOT   9633792
#define EPSV  1e-5f

// ---------------- scratch ----------------------------------------------------
__device__ float g_h1[TOT];
__device__ float g_d [TOT];
__device__ float g_xlr[TOT];
__device__ float g_xtd[TOT];
__device__ float g_t [TOT];
__device__ float g_p1[BATCH * 25 * 2];
__device__ float g_p2[BATCH * 192 * 2];
__device__ float g_p3[BATCH * 25 * 2];

// Fast gelu: 0.5x(1+erf(x/sqrt2)) with A&S 7.1.26 erf (|eps|<=1.5e-7).
__device__ __forceinline__ float gelu_f(float x) {
    const float z = fabsf(x) * 0.7071067811865476f;
    const float t = __fdividef(1.0f, 1.0f + 0.3275911f * z);
    const float e = __expf(-z * z);
    float p = t * (0.254829592f + t * (-0.284496736f + t * (1.421413741f +
              t * (-1.453152027f + t * 1.061405429f))));
    float er = 1.0f - p * e;
    er = copysignf(er, x);
    return 0.5f * x * (1.0f + er);
}

__device__ __forceinline__ uint32_t pack2(float lo, float hi) {
    __nv_bfloat162 t = __floats2bfloat162_rn(lo, hi);
    return *(uint32_t*)&t;
}

__device__ __forceinline__ void mma16816(float& d0, float& d1, float& d2, float& d3,
                                         uint32_t a0, uint32_t a1, uint32_t a2, uint32_t a3,
                                         uint32_t b0, uint32_t b1) {
    asm volatile(
        "mma.sync.aligned.m16n8k16.row.col.f32.bf16.bf16.f32 "
        "{%0,%1,%2,%3}, {%4,%5,%6,%7}, {%8,%9}, {%0,%1,%2,%3};"
        : "+f"(d0), "+f"(d1), "+f"(d2), "+f"(d3)
        : "r"(a0), "r"(a1), "r"(a2), "r"(a3), "r"(b0), "r"(b1));
}

__device__ __forceinline__ void ldsm_x4(uint32_t& r0, uint32_t& r1,
                                        uint32_t& r2, uint32_t& r3, uint32_t addr) {
    asm volatile("ldmatrix.sync.aligned.m8n8.x4.shared.b16 {%0,%1,%2,%3}, [%4];"
                 : "=r"(r0), "=r"(r1), "=r"(r2), "=r"(r3) : "r"(addr));
}

__device__ __forceinline__ uint32_t smem_addr(const void* p) {
    return (uint32_t)__cvta_generic_to_shared(p);
}

// warp-0 inline GN stats from npart (sum,sumsq) pairs -> red[0]=mu, red[1]=rstd
__device__ __forceinline__ void stats_warp0(const float* __restrict__ part,
                                            int b, int npart, int warp, int lane,
                                            float* red) {
    if (warp == 0) {
        float s1 = 0.f, s2 = 0.f;
        for (int i = lane; i < npart; i += 32) {
            s1 += part[((size_t)b * npart + i) * 2];
            s2 += part[((size_t)b * npart + i) * 2 + 1];
        }
#pragma unroll
        for (int off = 16; off > 0; off >>= 1) {
            s1 += __shfl_xor_sync(0xFFFFFFFFu, s1, off);
            s2 += __shfl_xor_sync(0xFFFFFFFFu, s2, off);
        }
        if (lane == 0) {
            float mu  = s1 / (float)CHW;
            float var = s2 / (float)CHW - mu * mu;
            red[0] = mu;
            red[1] = rsqrtf(var + EPSV);
        }
    }
    __syncthreads();
}

// A-operand: weight 16x16 bf16 hi/lo fragments from global (row o_row)
__device__ __forceinline__ void load_afrags(const float* __restrict__ w, int o_row,
                                            int tig, uint32_t aH[6][4], uint32_t aL[6][4]) {
    const float* w0 = w + (size_t)o_row * CH;
#pragma unroll
    for (int s = 0; s < 6; s++) {
        const int c0 = s * 16 + 2 * tig;
#pragma unroll
        for (int q = 0; q < 4; q++) {
            const int roff = (q & 1) ? 8 * CH : 0;
            const int coff = (q & 2) ? 8 : 0;
            const float f0 = __ldg(&w0[roff + c0 + coff]);
            const float f1 = __ldg(&w0[roff + c0 + coff + 1]);
            const __nv_bfloat16 h0 = __float2bfloat16_rn(f0);
            const __nv_bfloat16 h1 = __float2bfloat16_rn(f1);
            aH[s][q] = pack2(__bfloat162float(h0), __bfloat162float(h1));
            aL[s][q] = pack2(f0 - __bfloat162float(h0), f1 - __bfloat162float(h1));
        }
    }
}

#define BSTR 104   // elements per B row (52 words; conflict-free ldmatrix phases)

// ---------------- 96x96 conv1x1 (mma.sync, split-bf16, ldmatrix B) -----------
// INM: 2 = gn-affine input (stats inline from part_in, npart=25)
// OUTM: 1 = gelu. PART: emit partials. ACC: += existing out.
template<int INM, int OUTM, int PART, int ACC>
__global__ void __launch_bounds__(192, 4) gemm_mma(
    const float* __restrict__ in, const float* __restrict__ w,
    const float* __restrict__ bias, float* __restrict__ out,
    const float* __restrict__ part_in, const float* __restrict__ gw,
    const float* __restrict__ gb, float* __restrict__ part)
{
    extern __shared__ char dsm[];
    __nv_bfloat16* bhm = (__nv_bfloat16*)dsm;            // [128][104] hi
    __nv_bfloat16* blm = bhm + 128 * BSTR;               // [128][104] lo
    uint32_t* bh32 = (uint32_t*)bhm;
    uint32_t* bl32 = (uint32_t*)blm;
    float* red = (float*)(dsm + 128 * BSTR * 2 * 2);

    const int b    = blockIdx.y;
    const int p0   = blockIdx.x * 128;
    const int tid  = threadIdx.x;
    const int warp = tid >> 5, lane = tid & 31;
    const int gid  = lane >> 2, tig = lane & 3;
    const int o0   = warp * 16;

    float mu = 0.f, rs = 0.f;
    if (INM == 2) {
        stats_warp0(part_in, b, 25, warp, lane, red);
        mu = red[0]; rs = red[1];
        __syncthreads();
    }

    // ---- B fill: (c,c+1) pair-packed, one STS.32 per buffer ---------------
    const float* inb = in + (size_t)b * CHW + p0;
    for (int i = tid; i < 48 * 128; i += 192) {
        const int px = i & 127, cp = i >> 7;
        const int c = cp * 2;
        float v0 = 0.f, v1 = 0.f;
        if (p0 + px < HW) {
            v0 = inb[(size_t)c * HW + px];
            v1 = inb[(size_t)(c + 1) * HW + px];
        }
        if (INM == 2) {
            float a0 = rs * gw[c],     bb0 = gb[c]     - mu * a0;
            float a1 = rs * gw[c + 1], bb1 = gb[c + 1] - mu * a1;
            v0 = v0 * a0 + bb0;
            v1 = v1 * a1 + bb1;
        }
        const __nv_bfloat16 h0 = __float2bfloat16_rn(v0);
        const __nv_bfloat16 h1 = __float2bfloat16_rn(v1);
        const float l0 = v0 - __bfloat162float(h0);
        const float l1 = v1 - __bfloat162float(h1);
        const int wi = px * 52 + cp;
        bh32[wi] = pack2(__bfloat162float(h0), __bfloat162float(h1));
        bl32[wi] = pack2(l0, l1);
    }

    uint32_t aH[6][4], aL[6][4];
    load_afrags(w, o0 + gid, tig, aH, aL);
    __syncthreads();

    // ldmatrix lane pointers: lane L -> matrix mL = L>>3, row rL = L&7.
    // group g covers s-pair (2g, 2g+1): k-offset = (2g + (mL>>1))*16 + (mL&1)*8
    const int rL = lane & 7, mL = lane >> 3;
    uint32_t hadr[3], ladr[3];
#pragma unroll
    for (int g = 0; g < 3; g++) {
        const uint32_t eoff = (uint32_t)(rL * BSTR + (2 * g + (mL >> 1)) * 16 + (mL & 1) * 8);
        hadr[g] = smem_addr(bhm + eoff);
        ladr[g] = smem_addr(blm + eoff);
    }
    const uint32_t ntstep = 8 * BSTR * 2;   // bytes per nt-tile of 8 px rows

    const float bias0 = bias[o0 + gid];
    const float bias1 = bias[o0 + gid + 8];
    float s1 = 0.f, s2 = 0.f;
    float* ob = out + (size_t)b * CHW;

    for (int nt = 0; nt < 16; nt++) {
        float d0 = 0.f, d1 = 0.f, d2 = 0.f, d3 = 0.f;
        // interleaved ldsm+mma per k-group: only 8 B regs live at a time
#pragma unroll
        for (int g = 0; g < 3; g++) {
            uint32_t h0, h1, h2, h3, l0, l1, l2, l3;
            ldsm_x4(h0, h1, h2, h3, hadr[g]);
            ldsm_x4(l0, l1, l2, l3, ladr[g]);
            hadr[g] += ntstep;
            ladr[g] += ntstep;
            const int sa = 2 * g, sb = 2 * g + 1;
            mma16816(d0, d1, d2, d3, aH[sa][0], aH[sa][1], aH[sa][2], aH[sa][3], h0, h1);
            mma16816(d0, d1, d2, d3, aL[sa][0], aL[sa][1], aL[sa][2], aL[sa][3], h0, h1);
            mma16816(d0, d1, d2, d3, aH[sa][0], aH[sa][1], aH[sa][2], aH[sa][3], l0, l1);
            mma16816(d0, d1, d2, d3, aH[sb][0], aH[sb][1], aH[sb][2], aH[sb][3], h2, h3);
            mma16816(d0, d1, d2, d3, aL[sb][0], aL[sb][1], aL[sb][2], aL[sb][3], h2, h3);
            mma16816(d0, d1, d2, d3, aH[sb][0], aH[sb][1], aH[sb][2], aH[sb][3], l2, l3);
        }
        const int px = p0 + nt * 8 + 2 * tig;
        if (px < HW) {
            float v00 = d0 + bias0, v01 = d1 + bias0;
            float v10 = d2 + bias1, v11 = d3 + bias1;
            if (OUTM == 1) {
                v00 = gelu_f(v00); v01 = gelu_f(v01);
                v10 = gelu_f(v10); v11 = gelu_f(v11);
            }
            float* p00 = ob + (size_t)(o0 + gid) * HW + px;
            float* p10 = ob + (size_t)(o0 + gid + 8) * HW + px;
            if (ACC) {
                float2 t0 = *(float2*)p00; v00 += t0.x; v01 += t0.y;
                float2 t1 = *(float2*)p10; v10 += t1.x; v11 += t1.y;
            }
            *(float2*)p00 = make_float2(v00, v01);
            *(float2*)p10 = make_float2(v10, v11);
            if (PART) {
                s1 += v00 + v01 + v10 + v11;
                s2 += v00 * v00 + v01 * v01 + v10 * v10 + v11 * v11;
            }
        }
    }

    if (PART) {
#pragma unroll
        for (int off = 16; off > 0; off >>= 1) {
            s1 += __shfl_xor_sync(0xFFFFFFFFu, s1, off);
            s2 += __shfl_xor_sync(0xFFFFFFFFu, s2, off);
        }
        __syncthreads();
        if (lane == 0) { red[warp] = s1; red[8 + warp] = s2; }
        __syncthreads();
        if (tid == 0) {
            float t1 = 0.f, t2 = 0.f;
#pragma unroll
            for (int i = 0; i < 6; i++) { t1 += red[i]; t2 += red[8 + i]; }
            float* pp = part + ((size_t)b * gridDim.x + blockIdx.x) * 2;
            pp[0] = t1; pp[1] = t2;
        }
    }
}

// ---------------- depthwise 3x3, fused GN1+GELU (stats inline) ---------------
__global__ void __launch_bounds__(256) dw_k(
    const float* __restrict__ in, const float* __restrict__ part_in,
    const float* __restrict__ gw, const float* __restrict__ gb,
    const float* __restrict__ dww, const float* __restrict__ dwb,
    float* __restrict__ out, float* __restrict__ part)
{
    __shared__ float tile[30][58];
    __shared__ float red[512];
    const int rt = blockIdx.x;
    const int c  = blockIdx.y;
    const int b  = blockIdx.z;
    const int tid = threadIdx.x;
    const int warp = tid >> 5, lane = tid & 31;

    stats_warp0(part_in, b, 25, warp, lane, red);
    const float mu = red[0], rs = red[1];
    __syncthreads();

    const float a  = rs * gw[c];
    const float bb = gb[c] - mu * a;
    const float* inb = in + (size_t)(b * CH + c) * HW;
    const int r0 = rt * 28;

    for (int i = tid; i < 30 * 58; i += 256) {
        int rr = i / 58, cc = i % 58;
        int gr = r0 - 1 + rr, gc = cc - 1;
        float v = 0.f;
        if (gr >= 0 && gr < HH && gc >= 0 && gc < WW)
            v = gelu_f(inb[gr * WW + gc] * a + bb);
        tile[rr][cc] = v;
    }
    float wd[9];
#pragma unroll
    for (int i = 0; i < 9; i++) wd[i] = dww[c * 9 + i];
    const float bd = dwb[c];
    __syncthreads();

    float s1 = 0.f, s2 = 0.f;
    for (int p = tid; p < 28 * 56; p += 256) {
        int lr = p / 56, lc = p % 56;
        float accv = bd;
#pragma unroll
        for (int i = 0; i < 3; i++)
#pragma unroll
            for (int j = 0; j < 3; j++)
                accv = fmaf(wd[i * 3 + j], tile[lr + i][lc + j], accv);
        out[(size_t)(b * CH + c) * HW + (r0 + lr) * WW + lc] = accv;
        s1 += accv; s2 += accv * accv;
    }
    red[tid] = s1; red[256 + tid] = s2;
    __syncthreads();
    for (int off = 128; off > 0; off >>= 1) {
        if (tid < off) {
            red[tid] += red[tid + off];
            red[256 + tid] += red[256 + tid + off];
        }
        __syncthreads();
    }
    if (tid == 0) {
        float* pp = part + ((size_t)b * 192 + c * 2 + rt) * 2;
        pp[0] = red[0]; pp[1] = red[256];
    }
}

// ---------------- fused LIF (stats inline, H and W scans, 4x4 tile) ----------
__global__ void __launch_bounds__(256) lif_k(
    const float* __restrict__ in, const float* __restrict__ part_in,
    const float* __restrict__ gw, const float* __restrict__ gb,
    const float* __restrict__ tau1_p, const float* __restrict__ vth1_p,
    const float* __restrict__ tau2_p, const float* __restrict__ vth2_p,
    float* __restrict__ xlr, float* __restrict__ xtd)
{
    __shared__ float red[2];
    const int tid = threadIdx.x;
    const int warp = tid >> 5, lane = tid & 31;
    const int idx = blockIdx.x * 256 + tid;

    const int wg = idx % 14;
    const int hg = (idx / 14) % 14;
    const int c  = (idx / 196) % CH;
    const int b  = idx / (196 * CH);
    const bool ok = idx < BATCH * CH * 14 * 14;

    const int b0 = (blockIdx.x * 256) / 18816;
    if (warp == 0) {
        float s1 = 0.f, s2 = 0.f;
        for (int i = lane; i < 192; i += 32) {
            s1 += part_in[((size_t)b0 * 192 + i) * 2];
            s2 += part_in[((size_t)b0 * 192 + i) * 2 + 1];
        }
#pragma unroll
        for (int off = 16; off > 0; off >>= 1) {
            s1 += __shfl_xor_sync(0xFFFFFFFFu, s1, off);
            s2 += __shfl_xor_sync(0xFFFFFFFFu, s2, off);
        }
        if (lane == 0) {
            float m = s1 / (float)CHW;
            red[0] = m;
            red[1] = rsqrtf(s2 / (float)CHW - m * m + EPSV);
        }
    }
    __syncthreads();
    float mu = red[0], rs = red[1];
    if (ok && b != b0) {   // boundary block: recompute serially (rare)
        float s1 = 0.f, s2 = 0.f;
        for (int i = 0; i < 192; i++) {
            s1 += part_in[((size_t)b * 192 + i) * 2];
            s2 += part_in[((size_t)b * 192 + i) * 2 + 1];
        }
        mu = s1 / (float)CHW;
        rs = rsqrtf(s2 / (float)CHW - mu * mu + EPSV);
    }
    if (!ok) return;

    const float a  = rs * gw[c];
    const float bb = gb[c] - mu * a;
    const float tau1 = tau1_p[0], vth1 = vth1_p[0];
    const float tau2 = tau2_p[0], vth2 = vth2_p[0];

    const size_t base = (size_t)(b * CH + c) * HW + (size_t)(hg * 4) * WW + wg * 4;

    float g[4][4];
#pragma unroll
    for (int i = 0; i < 4; i++) {
        float4 v = *(const float4*)(in + base + (size_t)i * WW);
        g[i][0] = gelu_f(v.x * a + bb);
        g[i][1] = gelu_f(v.y * a + bb);
        g[i][2] = gelu_f(v.z * a + bb);
        g[i][3] = gelu_f(v.w * a + bb);
    }
#pragma unroll
    for (int i = 0; i < 4; i++) {
        float u = 0.f, s = 0.f, y[4];
#pragma unroll
        for (int j = 0; j < 4; j++) {
            u = g[i][j] + tau2 * u * (1.f - s);
            s = (u > vth2) ? 1.f : 0.f;
            y[j] = u * s;
        }
        *(float4*)(xtd + base + (size_t)i * WW) = make_float4(y[0], y[1], y[2], y[3]);
    }
    float yl[4][4];
#pragma unroll
    for (int j = 0; j < 4; j++) {
        float u = 0.f, s = 0.f;
#pragma unroll
        for (int i = 0; i < 4; i++) {
            u = g[i][j] + tau1 * u * (1.f - s);
            s = (u > vth1) ? 1.f : 0.f;
            yl[i][j] = u * s;
        }
    }
#pragma unroll
    for (int i = 0; i < 4; i++)
        *(float4*)(xlr + base + (size_t)i * WW) =
            make_float4(yl[i][0], yl[i][1], yl[i][2], yl[i][3]);
}

// ---------------- host pipeline (6 launches) ---------------------------------
#define GEMM_SMEM (128 * BSTR * 2 * 2 + 256)

extern "C" void kernel_launch(void* const* d_in, const int* in_sizes, int n_in,
                              void* d_out, int out_size)
{
    const float* x    = (const float*)d_in[0];
    const float* w1   = (const float*)d_in[1];
    const float* b1   = (const float*)d_in[2];
    const float* n1w  = (const float*)d_in[3];
    const float* n1b  = (const float*)d_in[4];
    const float* dww  = (const float*)d_in[5];
    const float* dwb  = (const float*)d_in[6];
    const float* n2w  = (const float*)d_in[7];
    const float* n2b  = (const float*)d_in[8];
    const float* tau1 = (const float*)d_in[9];
    const float* vth1 = (const float*)d_in[10];
    const float* tau2 = (const float*)d_in[11];
    const float* vth2 = (const float*)d_in[12];
    const float* w21  = (const float*)d_in[13];
    const float* b21  = (const float*)d_in[14];
    const float* w22  = (const float*)d_in[15];
    const float* b22  = (const float*)d_in[16];
    const float* n3w  = (const float*)d_in[17];
    const float* n3b  = (const float*)d_in[18];
    const float* w3   = (const float*)d_in[19];
    const float* b3   = (const float*)d_in[20];
    float* out = (float*)d_out;

    float *h1, *dd, *xlr, *xtd, *tt, *p1, *p2, *p3;
    cudaGetSymbolAddress((void**)&h1,  g_h1);
    cudaGetSymbolAddress((void**)&dd,  g_d);
    cudaGetSymbolAddress((void**)&xlr, g_xlr);
    cudaGetSymbolAddress((void**)&xtd, g_xtd);
    cudaGetSymbolAddress((void**)&tt,  g_t);
    cudaGetSymbolAddress((void**)&p1,  g_p1);
    cudaGetSymbolAddress((void**)&p2,  g_p2);
    cudaGetSymbolAddress((void**)&p3,  g_p3);

    cudaFuncSetAttribute(gemm_mma<0,0,1,0>, cudaFuncAttributeMaxDynamicSharedMemorySize, GEMM_SMEM);
    cudaFuncSetAttribute(gemm_mma<0,1,0,0>, cudaFuncAttributeMaxDynamicSharedMemorySize, GEMM_SMEM);
    cudaFuncSetAttribute(gemm_mma<0,1,1,1>, cudaFuncAttributeMaxDynamicSharedMemorySize, GEMM_SMEM);
    cudaFuncSetAttribute(gemm_mma<2,0,0,0>, cudaFuncAttributeMaxDynamicSharedMemorySize, GEMM_SMEM);

    dim3 gg(25, BATCH);

    // 1. conv1 -> h1, GN1 partials
    gemm_mma<0,0,1,0><<<gg, 192, GEMM_SMEM>>>(x, w1, b1, h1, nullptr, nullptr, nullptr, p1);

    // 2. gelu(gn1(h1)) -> dwconv -> dd, GN2 partials (GN1 stats inline)
    dw_k<<<dim3(2, CH, BATCH), 256>>>(h1, p1, n1w, n1b, dww, dwb, dd, p2);

    // 3. fused LIF (GN2 stats inline)
    const int nlif = BATCH * CH * 14 * 14;
    lif_k<<<(nlif + 255) / 256, 256>>>(dd, p2, n2w, n2b, tau1, vth1, tau2, vth2, xlr, xtd);

    // 4. tt = gelu(w21@xlr+b21)
    gemm_mma<0,1,0,0><<<gg, 192, GEMM_SMEM>>>(xlr, w21, b21, tt, nullptr, nullptr, nullptr, nullptr);

    // 5. tt += gelu(w22@xtd+b22), GN3 partials
    gemm_mma<0,1,1,1><<<gg, 192, GEMM_SMEM>>>(xtd, w22, b22, tt, nullptr, nullptr, nullptr, p3);

    // 6. out = conv3 @ gn3(tt)  (GN3 stats inline)
    gemm_mma<2,0,0,0><<<gg, 192, GEMM_SMEM>>>(tt, w3, b3, out, p3, n3w, n3b, nullptr);
}